// round 15
// baseline (speedup 1.0000x reference)
#include <cuda_runtime.h>
#include <cstdint>
#include <math.h>

// Problem constants
#define Bb   256
#define Tt   1024
#define Hh   164
#define JH   82          // hidden slice per CTA (M-split across 2-CTA cluster)
#define NTH  384         // 12 warps; 328 compute threads
#define NCTA 128         // 64 clusters x 2
#define HSL  84          // h k-pair slots per parity (82 real + 2 zero pad)
#define HBUF (HSL * 32)  // 2688
#define RPW  11          // k-pairs in registers per window
#define SPW  10          // k-pairs in smem per window
#define HPUSH 1312       // bytes per h half-push (41 k-pairs * 32B)

// shared memory layout (bytes)
#define OFF_WSM   0
#define SZ_WSM    (2 * SPW * 328 * 16)      // 104960
#define OFF_HQ    (OFF_WSM + SZ_WSM)        // 104960 (16B aligned)
#define SZ_HQ     (2 * HBUF)                // 5376
#define OFF_GB    (OFF_HQ + SZ_HQ)          // 110336
#define SZ_GB     (656 * 16)                // 10496: gb4[(u*2+ab)*164+g]
#define OFF_PRFP  (OFF_GB + SZ_GB)          // 120832: peer pred sums [par][r]
#define SZ_PRFP   32
#define OFF_PRFL  (OFF_PRFP + SZ_PRFP)      // 120864: local pred sums [par][r]
#define SZ_PRFL   32
#define OFF_XQ    (OFF_PRFL + SZ_PRFL)      // 120896
#define SZ_XQ     (2 * 8 * 16)              // 256
#define OFF_WIH   (OFF_XQ + SZ_XQ)          // 121152: wihs[(ab*7+i-1)*164+g]
#define SZ_WIH    (14 * 164 * 4)            // 9184
#define OFF_W04   (OFF_WIH + SZ_WIH)        // 130336: w_ih[:,0] float4 per jj
#define SZ_W04    (82 * 16)
#define OFF_WO    (OFF_W04 + SZ_W04)        // 131648 (8B aligned)
#define SZ_WO     (82 * 4)
#define OFF_B2    (OFF_WO + SZ_WO)          // 131976 (8B aligned)
#define SZ_B2     (164 * 8)
#define OFF_MBAR  ((OFF_B2 + SZ_B2 + 15) & ~15)
#define SMEM_TOTAL (OFF_MBAR + 16)

typedef unsigned long long ull;

__device__ __forceinline__ float sigmoidf_(float v) {
    return 1.0f / (1.0f + expf(-v));
}
__device__ __forceinline__ ull pack2_(float a, float b) {
    ull r; asm("mov.b64 %0, {%1, %2};" : "=l"(r) : "f"(a), "f"(b)); return r;
}
__device__ __forceinline__ void unpack2_(ull v, float& a, float& b) {
    asm("mov.b64 {%0, %1}, %2;" : "=f"(a), "=f"(b) : "l"(v));
}
__device__ __forceinline__ void fma2_(ull& acc, ull a, ull b) {
    asm("fma.rn.f32x2 %0, %1, %2, %0;" : "+l"(acc) : "l"(a), "l"(b));
}
__device__ __forceinline__ void st_remote_f32d(uint32_t raddr, float v) {
    asm volatile("st.shared::cluster.f32 [%0], %1;" :: "r"(raddr), "f"(v) : "memory");
}
__device__ __forceinline__ void mbar_arrive_release(uint32_t remote_mbar) {
    asm volatile("mbarrier.arrive.release.cluster.shared::cluster.b64 _, [%0];"
                 :: "r"(remote_mbar) : "memory");
}
__device__ __forceinline__ void mbar_arrive_expect_tx(uint32_t mbar, uint32_t tx) {
    asm volatile("mbarrier.arrive.expect_tx.shared.b64 _, [%0], %1;"
                 :: "r"(mbar), "r"(tx) : "memory");
}
__device__ __forceinline__ void mbar_arrive_local(uint32_t mbar) {
    asm volatile("mbarrier.arrive.shared.b64 _, [%0];" :: "r"(mbar) : "memory");
}
__device__ __forceinline__ void bulk_push_peer(uint32_t peer_dst, uint32_t local_src,
                                               uint32_t bytes, uint32_t peer_mbar) {
    asm volatile(
        "cp.async.bulk.shared::cluster.shared::cta.mbarrier::complete_tx::bytes "
        "[%0], [%1], %2, [%3];"
        :: "r"(peer_dst), "r"(local_src), "r"(bytes), "r"(peer_mbar) : "memory");
}
__device__ __forceinline__ void mbar_wait(uint32_t mbar, uint32_t parity) {
    uint32_t done;
    asm volatile(
        "{\n\t.reg .pred p;\n\t"
        "mbarrier.try_wait.parity.acquire.cluster.shared::cta.b64 p, [%1], %2;\n\t"
        "selp.b32 %0, 1, 0, p;\n\t}"
        : "=r"(done) : "r"(mbar), "r"(parity) : "memory");
    while (!done) {
        asm volatile(
            "{\n\t.reg .pred p;\n\t"
            "mbarrier.try_wait.parity.acquire.cluster.shared::cta.b64 p, [%1], %2, 0x989680;\n\t"
            "selp.b32 %0, 1, 0, p;\n\t}"
            : "=r"(done) : "r"(mbar), "r"(parity) : "memory");
    }
}

extern "C" __global__ void __launch_bounds__(NTH, 1) __cluster_dims__(2, 1, 1)
lstm_anom_kernel(const float* __restrict__ x,
                 const float* __restrict__ Wih,
                 const float* __restrict__ Whh,
                 const float* __restrict__ bih,
                 const float* __restrict__ bhh,
                 const float* __restrict__ Wout,
                 const float* __restrict__ bout,
                 float* __restrict__ out)
{
    extern __shared__ char smem[];
    ulonglong2* Wsm2 = (ulonglong2*)(smem + OFF_WSM);
    float4* gb4  = (float4*)(smem + OFF_GB);
    const float* gbf = (const float*)(smem + OFF_GB);
    float*  prfp = (float*)(smem + OFF_PRFP);
    float*  prfl = (float*)(smem + OFF_PRFL);
    float*  xqf  = (float*)(smem + OFF_XQ);
    float*  wihs = (float*)(smem + OFF_WIH);
    float4* w04  = (float4*)(smem + OFF_W04);
    float*  wo   = (float*)(smem + OFF_WO);
    float2* b2   = (float2*)(smem + OFF_B2);

    const int tid       = threadIdx.x;
    const uint32_t rank = (uint32_t)(blockIdx.x & 1);
    const uint32_t peer = rank ^ 1u;
    const int cluster   = blockIdx.x >> 1;
    const int row0      = cluster * 4;

    const uint32_t smem_b = (uint32_t)__cvta_generic_to_shared(smem);
    const uint32_t mbar_b = smem_b + OFF_MBAR;
    uint32_t peer_b;
    asm("mapa.shared::cluster.u32 %0, %1, %2;" : "=r"(peer_b) : "r"(smem_b), "r"(peer));
    const uint32_t peer_mbar = peer_b + OFF_MBAR;

    // ---------- roles ----------
    const bool active = (tid < 328);
    const int u = (tid >= 164) ? 1 : 0;        // k sub-window
    const int g = active ? (tid - u * 164) : 0;
    const int prank = (int)(rank ^ 1u);

    // ---------- one-time init ----------
    ull wLA[RPW], wLB[RPW], wPA[RPW], wPB[RPW];
    if (active) {
        int gt  = g / JH;
        int jj0 = g - gt * JH;
        int RA  = gt * Hh + (int)rank * JH + jj0;        // gate i (gt0) / f (gt1)
        int RB  = (gt + 2) * Hh + (int)rank * JH + jj0;  // gate g / o
        const ull* wrA = (const ull*)(Whh + (size_t)RA * Hh);
        const ull* wrB = (const ull*)(Whh + (size_t)RB * Hh);
#pragma unroll
        for (int w = 0; w < 2; w++) {
            int half = w ? prank : (int)rank;
            int kb = half * 41 + u * 21;
#pragma unroll
            for (int kk = 0; kk < 21; kk++) {
                bool real = (u * 21 + kk) < 41;
                ull vAw = real ? wrA[kb + kk] : 0ull;
                ull vBw = real ? wrB[kb + kk] : 0ull;
                if (kk < RPW) {
                    if (w == 0) { wLA[kk] = vAw; wLB[kk] = vBw; }
                    else        { wPA[kk] = vAw; wPB[kk] = vBw; }
                } else {
                    Wsm2[(w * SPW + kk - RPW) * 328 + tid] = make_ulonglong2(vAw, vBw);
                }
            }
        }
        if (u == 0) {
#pragma unroll
            for (int i = 1; i < 8; i++) {
                wihs[(0 * 7 + i - 1) * 164 + g] = Wih[RA * 8 + i];
                wihs[(1 * 7 + i - 1) * 164 + g] = Wih[RB * 8 + i];
            }
            b2[g] = make_float2(bih[RA] + bhh[RA], bih[RB] + bhh[RB]);
        }
    }
    if (tid < JH) {
        int base = (int)rank * JH + tid;
        w04[tid] = make_float4(Wih[(0 * Hh + base) * 8], Wih[(1 * Hh + base) * 8],
                               Wih[(2 * Hh + base) * 8], Wih[(3 * Hh + base) * 8]);
        wo[tid] = Wout[base];
    }
    for (int idx = tid; idx < (SZ_HQ / 4); idx += NTH)
        ((float*)(smem + OFF_HQ))[idx] = 0.f;
    if (tid < 8) { prfp[tid] = 0.f; prfl[tid] = 0.f; }
    if (tid < 32) {
        int i = tid >> 2, r = tid & 3;
        xqf[(0 * 8 + i) * 4 + r] = x[((size_t)((row0 + r) * Tt)) * 8 + i];
    }
    if (tid == 0) {
        // per phase: 1 self-arm + 4 peer pred arrives (h comes as 1312B tx)
        asm volatile("mbarrier.init.shared.b64 [%0], 5;" :: "r"(mbar_b) : "memory");
        asm volatile("mbarrier.init.shared.b64 [%0], 5;" :: "r"(mbar_b + 8) : "memory");
    }
    const float bout_r = bout[0];
    float c_r = 0.f;
    const int jj = tid >> 2, rr = tid & 3;
    int ph0 = 0, ph1 = 0;

    __syncthreads();
    asm volatile("barrier.cluster.arrive.aligned;" ::: "memory");
    asm volatile("barrier.cluster.wait.aligned;" ::: "memory");

    for (int t = 0; t < Tt; ++t) {
        const int cur = t & 1;
        const int nxt = cur ^ 1;

        // ---- crew (warp 11 idle lanes):
        //      lane 356: arm my mbar for next phase + bulk-push h[cur] local half;
        //      lanes 357-360: pred dot over local h[cur] + push + arrive. ----
        if (tid >= 356) {
            if (tid == 356) {
                if (t + 1 < Tt) mbar_arrive_expect_tx(mbar_b + (uint32_t)(nxt * 8), HPUSH);
                else            mbar_arrive_local(mbar_b + (uint32_t)(nxt * 8));
                if (t) {
                    uint32_t off = (uint32_t)(OFF_HQ + cur * HBUF + (int)rank * HPUSH);
                    asm volatile("fence.proxy.async.shared::cta;" ::: "memory");
                    bulk_push_peer(peer_b + off, smem_b + off, HPUSH,
                                   peer_mbar + (uint32_t)(cur * 8));
                }
            } else if (tid < 361 && t) {
                int r = tid - 357;
                const char* hb = smem + OFF_HQ + cur * HBUF + (int)rank * HPUSH;
                const float2* wo2 = (const float2*)wo;
                float s0 = 0.f, s1 = 0.f, s2 = 0.f, s3 = 0.f;
#pragma unroll 5
                for (int j2 = 0; j2 < 40; j2 += 2) {
                    float2 h0 = *(const float2*)(hb + j2 * 32 + r * 8);
                    float2 h1 = *(const float2*)(hb + (j2 + 1) * 32 + r * 8);
                    float2 w0 = wo2[j2];
                    float2 w1 = wo2[j2 + 1];
                    s0 += h0.x * w0.x; s1 += h0.y * w0.y;
                    s2 += h1.x * w1.x; s3 += h1.y * w1.y;
                }
                {   // j2 = 40 (last pair: jj 80, 81)
                    float2 h0 = *(const float2*)(hb + 40 * 32 + r * 8);
                    float2 w0 = wo2[40];
                    s0 += h0.x * w0.x; s1 += h0.y * w0.y;
                }
                float s = (s0 + s1) + (s2 + s3);
                prfl[nxt * 4 + r] = s;
                st_remote_f32d(peer_b + (uint32_t)(OFF_PRFP + (nxt * 4 + r) * 4), s);
                mbar_arrive_release(peer_mbar + (uint32_t)(cur * 8));
            }
        }

        // ---- phase L: GEMV over LOCAL k sub-window (21 k-pairs) ----
        ull acc[8];   // [0..3] = row A r0..3, [4..7] = row B
        if (active) {
            const float4* xv4 = (const float4*)(smem + OFF_XQ + cur * 128);
            if (u == 0) {
                float2 bb = b2[g];
                float a0 = bb.x, a1 = bb.x, a2 = bb.x, a3 = bb.x;
                float b0 = bb.y, b1 = bb.y, b2v = bb.y, b3 = bb.y;
#pragma unroll
                for (int i = 1; i < 5; i++) {     // features 1-4
                    float4 xv = xv4[i];
                    float wA = wihs[(0 * 7 + i - 1) * 164 + g];
                    float wB = wihs[(1 * 7 + i - 1) * 164 + g];
                    a0 += wA * xv.x; a1 += wA * xv.y; a2 += wA * xv.z; a3 += wA * xv.w;
                    b0 += wB * xv.x; b1 += wB * xv.y; b2v += wB * xv.z; b3 += wB * xv.w;
                }
                acc[0] = pack2_(a0, 0.f); acc[1] = pack2_(a1, 0.f);
                acc[2] = pack2_(a2, 0.f); acc[3] = pack2_(a3, 0.f);
                acc[4] = pack2_(b0, 0.f); acc[5] = pack2_(b1, 0.f);
                acc[6] = pack2_(b2v, 0.f); acc[7] = pack2_(b3, 0.f);
            } else {
                float a0 = 0.f, a1 = 0.f, a2 = 0.f, a3 = 0.f;
                float b0 = 0.f, b1 = 0.f, b2v = 0.f, b3 = 0.f;
#pragma unroll
                for (int i = 5; i < 8; i++) {     // features 5-7
                    float4 xv = xv4[i];
                    float wA = wihs[(0 * 7 + i - 1) * 164 + g];
                    float wB = wihs[(1 * 7 + i - 1) * 164 + g];
                    a0 += wA * xv.x; a1 += wA * xv.y; a2 += wA * xv.z; a3 += wA * xv.w;
                    b0 += wB * xv.x; b1 += wB * xv.y; b2v += wB * xv.z; b3 += wB * xv.w;
                }
                acc[0] = pack2_(a0, 0.f); acc[1] = pack2_(a1, 0.f);
                acc[2] = pack2_(a2, 0.f); acc[3] = pack2_(a3, 0.f);
                acc[4] = pack2_(b0, 0.f); acc[5] = pack2_(b1, 0.f);
                acc[6] = pack2_(b2v, 0.f); acc[7] = pack2_(b3, 0.f);
            }
            const char* hbL = smem + OFF_HQ + cur * HBUF + ((int)rank * 41 + u * 21) * 32;
#pragma unroll
            for (int kk = 0; kk < RPW; kk++) {
                ulonglong2 h01 = *(const ulonglong2*)(hbL + kk * 32);
                ulonglong2 h23 = *(const ulonglong2*)(hbL + kk * 32 + 16);
                fma2_(acc[0], wLA[kk], h01.x); fma2_(acc[4], wLB[kk], h01.x);
                fma2_(acc[1], wLA[kk], h01.y); fma2_(acc[5], wLB[kk], h01.y);
                fma2_(acc[2], wLA[kk], h23.x); fma2_(acc[6], wLB[kk], h23.x);
                fma2_(acc[3], wLA[kk], h23.y); fma2_(acc[7], wLB[kk], h23.y);
            }
#pragma unroll
            for (int kk = RPW; kk < 21; kk++) {
                ulonglong2 w2 = Wsm2[(0 * SPW + kk - RPW) * 328 + tid];
                ulonglong2 h01 = *(const ulonglong2*)(hbL + kk * 32);
                ulonglong2 h23 = *(const ulonglong2*)(hbL + kk * 32 + 16);
                fma2_(acc[0], w2.x, h01.x); fma2_(acc[4], w2.y, h01.x);
                fma2_(acc[1], w2.x, h01.y); fma2_(acc[5], w2.y, h01.y);
                fma2_(acc[2], w2.x, h23.x); fma2_(acc[6], w2.y, h23.x);
                fma2_(acc[3], w2.x, h23.y); fma2_(acc[7], w2.y, h23.y);
            }
        }

        // ---- wait for peer h-half (bulk tx) + pred (pushed this step by peer) ----
        if (t && (active || (tid >= 352 && tid < 356))) {
            uint32_t p = cur ? (uint32_t)ph1 : (uint32_t)ph0;
            mbar_wait(mbar_b + (uint32_t)(cur * 8), p);
            if (cur) ph1 ^= 1; else ph0 ^= 1;
        }

        if (active) {
            // ---- phase P: GEMV over PEER k sub-window ----
            const char* hbP = smem + OFF_HQ + cur * HBUF + (prank * 41 + u * 21) * 32;
#pragma unroll
            for (int kk = 0; kk < RPW; kk++) {
                ulonglong2 h01 = *(const ulonglong2*)(hbP + kk * 32);
                ulonglong2 h23 = *(const ulonglong2*)(hbP + kk * 32 + 16);
                fma2_(acc[0], wPA[kk], h01.x); fma2_(acc[4], wPB[kk], h01.x);
                fma2_(acc[1], wPA[kk], h01.y); fma2_(acc[5], wPB[kk], h01.y);
                fma2_(acc[2], wPA[kk], h23.x); fma2_(acc[6], wPB[kk], h23.x);
                fma2_(acc[3], wPA[kk], h23.y); fma2_(acc[7], wPB[kk], h23.y);
            }
#pragma unroll
            for (int kk = RPW; kk < 21; kk++) {
                ulonglong2 w2 = Wsm2[(1 * SPW + kk - RPW) * 328 + tid];
                ulonglong2 h01 = *(const ulonglong2*)(hbP + kk * 32);
                ulonglong2 h23 = *(const ulonglong2*)(hbP + kk * 32 + 16);
                fma2_(acc[0], w2.x, h01.x); fma2_(acc[4], w2.y, h01.x);
                fma2_(acc[1], w2.x, h01.y); fma2_(acc[5], w2.y, h01.y);
                fma2_(acc[2], w2.x, h23.x); fma2_(acc[6], w2.y, h23.x);
                fma2_(acc[3], w2.x, h23.y); fma2_(acc[7], w2.y, h23.y);
            }
            float lo, hi;
            float4 vA, vB;
            unpack2_(acc[0], lo, hi); vA.x = lo + hi;
            unpack2_(acc[1], lo, hi); vA.y = lo + hi;
            unpack2_(acc[2], lo, hi); vA.z = lo + hi;
            unpack2_(acc[3], lo, hi); vA.w = lo + hi;
            unpack2_(acc[4], lo, hi); vB.x = lo + hi;
            unpack2_(acc[5], lo, hi); vB.y = lo + hi;
            unpack2_(acc[6], lo, hi); vB.z = lo + hi;
            unpack2_(acc[7], lo, hi); vB.w = lo + hi;
            gb4[(u * 2 + 0) * 164 + g] = vA;
            gb4[(u * 2 + 1) * 164 + g] = vB;
        } else if (tid >= 352 && tid < 356) {
            // ---- pred finalize + anomaly x0 fix + gmem outputs ----
            int r = tid - 352, row = row0 + r;
            if (t > 0) {
                float pred = prfl[nxt * 4 + r] + prfp[nxt * 4 + r] + bout_r;
                float x0raw = xqf[(cur * 8 + 0) * 4 + r];
                float flag = 0.f, x0 = x0raw;
                if (fabsf(pred - x0raw) > 0.1f) { x0 = pred; flag = 1.f; }
                xqf[(cur * 8 + 0) * 4 + r] = x0;
                if (rank == 0) {
                    out[(size_t)row * Tt + (t - 1)] = pred;
                    out[(size_t)Bb * Tt + (size_t)row * Tt + t] = flag;
                }
            } else if (rank == 0) {
                out[(size_t)Bb * Tt + (size_t)row * Tt] = 0.f;
            }
        } else if (tid >= 361 && tid < 365 && (t + 1 < Tt)) {
            // ---- x prefetch (4 lanes x 2 features) ----
            int i = tid - 361;
#pragma unroll
            for (int r = 0; r < 4; r++) {
                xqf[(nxt * 8 + i) * 4 + r] =
                    x[((size_t)((row0 + r) * Tt + t + 1)) * 8 + i];
                xqf[(nxt * 8 + i + 4) * 4 + r] =
                    x[((size_t)((row0 + r) * Tt + t + 1)) * 8 + i + 4];
            }
        }
        __syncthreads();   // gate partials + fixed x0 + xqf[nxt] published

        // ---- activation, state update, LOCAL h store (no pred work) ----
        if (active) {
            float x0 = xqf[(cur * 8 + 0) * 4 + rr];
            float4 wz = w04[jj];
            float gi = gbf[((0 * 2 + 0) * 164 + jj) * 4 + rr]
                     + gbf[((1 * 2 + 0) * 164 + jj) * 4 + rr] + wz.x * x0;
            float gF = gbf[((0 * 2 + 0) * 164 + jj + 82) * 4 + rr]
                     + gbf[((1 * 2 + 0) * 164 + jj + 82) * 4 + rr] + wz.y * x0;
            float gg = gbf[((0 * 2 + 1) * 164 + jj) * 4 + rr]
                     + gbf[((1 * 2 + 1) * 164 + jj) * 4 + rr] + wz.z * x0;
            float go = gbf[((0 * 2 + 1) * 164 + jj + 82) * 4 + rr]
                     + gbf[((1 * 2 + 1) * 164 + jj + 82) * 4 + rr] + wz.w * x0;
            float iv = sigmoidf_(gi);
            float fv = sigmoidf_(gF);
            float gv = tanhf(gg);
            float ov = sigmoidf_(go);
            c_r = fv * c_r + iv * gv;
            float hn = ov * tanhf(c_r);

            int kg = (int)rank * JH + jj;
            *(float*)(smem + OFF_HQ + nxt * HBUF
                      + (kg >> 1) * 32 + rr * 8 + (kg & 1) * 4) = hn;   // local only
        }
        __syncthreads();   // h[nxt] published
    }

    // ---- tail: crew dot over final h (buffer 0), push sums, write col Tt-1 ----
    if (tid >= 357 && tid < 361) {
        int r = tid - 357;
        const char* hb = smem + OFF_HQ + 0 * HBUF + (int)rank * HPUSH;
        const float2* wo2 = (const float2*)wo;
        float s0 = 0.f, s1 = 0.f;
#pragma unroll 8
        for (int j2 = 0; j2 < 41; j2++) {
            float2 h0 = *(const float2*)(hb + j2 * 32 + r * 8);
            float2 w0 = wo2[j2];
            s0 += h0.x * w0.x; s1 += h0.y * w0.y;
        }
        float s = s0 + s1;
        prfl[0 * 4 + r] = s;
        st_remote_f32d(peer_b + (uint32_t)(OFF_PRFP + (0 * 4 + r) * 4), s);
        mbar_arrive_release(peer_mbar);
    }
    if (tid >= 352 && tid < 356) {
        mbar_wait(mbar_b, (uint32_t)ph0);
        if (rank == 0) {
            int r = tid - 352;
            float pred = prfl[0 * 4 + r] + prfp[0 * 4 + r] + bout_r;
            out[(size_t)(row0 + r) * Tt + (Tt - 1)] = pred;
        }
    }
}

extern "C" void kernel_launch(void* const* d_in, const int* in_sizes, int n_in,
                              void* d_out, int out_size) {
    (void)in_sizes; (void)n_in; (void)out_size;
    cudaFuncSetAttribute(lstm_anom_kernel,
                         cudaFuncAttributeMaxDynamicSharedMemorySize, SMEM_TOTAL);
    lstm_anom_kernel<<<NCTA, NTH, SMEM_TOTAL>>>(
        (const float*)d_in[0],   // x
        (const float*)d_in[1],   // W_ih
        (const float*)d_in[2],   // W_hh
        (const float*)d_in[3],   // b_ih
        (const float*)d_in[4],   // b_hh
        (const float*)d_in[5],   // W_out
        (const float*)d_in[6],   // b_out
        (float*)d_out);
}

// round 16
// speedup vs baseline: 1.1229x; 1.1229x over previous
#include <cuda_runtime.h>
#include <cstdint>
#include <math.h>

// Problem constants
#define Bb   256
#define Tt   1024
#define Hh   164
#define JH   82          // hidden slice per CTA (M-split across 2-CTA cluster)
#define NTH  384         // 12 warps; 328 compute threads
#define NCTA 128         // 64 clusters x 2
#define HSL  84          // h k-pair slots per parity (82 real + 2 zero pad)
#define HBUF (HSL * 32)  // 2688
#define RPL  8           // k-pairs in registers, phase L (latency-hidden)
#define SPL  13          // smem k-pairs, phase L
#define RPP  14          // k-pairs in registers, phase P (critical path)
#define SPP  7           // smem k-pairs, phase P
#define HPUSH 1312       // bytes per h half-push (41 k-pairs * 32B)

// shared memory layout (bytes)
#define OFF_WSM   0
#define SZ_WSM    ((SPL + SPP) * 328 * 16)  // 104960 (20 slots: 0-12 L, 13-19 P)
#define OFF_HQ    (OFF_WSM + SZ_WSM)        // 104960 (16B aligned)
#define SZ_HQ     (2 * HBUF)                // 5376
#define OFF_GB    (OFF_HQ + SZ_HQ)          // 110336
#define SZ_GB     (656 * 16)                // 10496: gb4[(u*2+ab)*164+g]
#define OFF_PW    (OFF_GB + SZ_GB)          // 120832
#define SZ_PW     (2 * 11 * 16)             // 352: pwf[par][w][r]
#define OFF_PRFP  (OFF_PW + SZ_PW)          // peer pred sums [par][r]
#define SZ_PRFP   32
#define OFF_XQ    (OFF_PRFP + SZ_PRFP)
#define SZ_XQ     (2 * 8 * 16)              // 256
#define OFF_WIH   (OFF_XQ + SZ_XQ)          // wihs[(ab*7+i-1)*164+g]
#define SZ_WIH    (14 * 164 * 4)            // 9184
#define OFF_W04   (OFF_WIH + SZ_WIH)        // w_ih[:,0] float4 per jj
#define SZ_W04    (82 * 16)
#define OFF_WO    (OFF_W04 + SZ_W04)
#define SZ_WO     (82 * 4)
#define OFF_B2    (OFF_WO + SZ_WO)          // (biasA,biasB) per g
#define SZ_B2     (164 * 8)
#define OFF_MBAR  ((OFF_B2 + SZ_B2 + 15) & ~15)
#define SMEM_TOTAL (OFF_MBAR + 16)

typedef unsigned long long ull;

__device__ __forceinline__ float sigmoidf_(float v) {
    return 1.0f / (1.0f + expf(-v));
}
__device__ __forceinline__ ull pack2_(float a, float b) {
    ull r; asm("mov.b64 %0, {%1, %2};" : "=l"(r) : "f"(a), "f"(b)); return r;
}
__device__ __forceinline__ void unpack2_(ull v, float& a, float& b) {
    asm("mov.b64 {%0, %1}, %2;" : "=f"(a), "=f"(b) : "l"(v));
}
__device__ __forceinline__ void fma2_(ull& acc, ull a, ull b) {
    asm("fma.rn.f32x2 %0, %1, %2, %0;" : "+l"(acc) : "l"(a), "l"(b));
}
__device__ __forceinline__ void st_remote_f32d(uint32_t raddr, float v) {
    asm volatile("st.shared::cluster.f32 [%0], %1;" :: "r"(raddr), "f"(v) : "memory");
}
__device__ __forceinline__ void mbar_arrive_release(uint32_t remote_mbar) {
    asm volatile("mbarrier.arrive.release.cluster.shared::cluster.b64 _, [%0];"
                 :: "r"(remote_mbar) : "memory");
}
__device__ __forceinline__ void mbar_arrive_expect_tx(uint32_t mbar, uint32_t tx) {
    asm volatile("mbarrier.arrive.expect_tx.shared.b64 _, [%0], %1;"
                 :: "r"(mbar), "r"(tx) : "memory");
}
__device__ __forceinline__ void mbar_arrive_local(uint32_t mbar) {
    asm volatile("mbarrier.arrive.shared.b64 _, [%0];" :: "r"(mbar) : "memory");
}
__device__ __forceinline__ void bulk_push_peer(uint32_t peer_dst, uint32_t local_src,
                                               uint32_t bytes, uint32_t peer_mbar) {
    asm volatile(
        "cp.async.bulk.shared::cluster.shared::cta.mbarrier::complete_tx::bytes "
        "[%0], [%1], %2, [%3];"
        :: "r"(peer_dst), "r"(local_src), "r"(bytes), "r"(peer_mbar) : "memory");
}
__device__ __forceinline__ void mbar_wait(uint32_t mbar, uint32_t parity) {
    uint32_t done;
    asm volatile(
        "{\n\t.reg .pred p;\n\t"
        "mbarrier.try_wait.parity.acquire.cluster.shared::cta.b64 p, [%1], %2;\n\t"
        "selp.b32 %0, 1, 0, p;\n\t}"
        : "=r"(done) : "r"(mbar), "r"(parity) : "memory");
    while (!done) {
        asm volatile(
            "{\n\t.reg .pred p;\n\t"
            "mbarrier.try_wait.parity.acquire.cluster.shared::cta.b64 p, [%1], %2, 0x989680;\n\t"
            "selp.b32 %0, 1, 0, p;\n\t}"
            : "=r"(done) : "r"(mbar), "r"(parity) : "memory");
    }
}

extern "C" __global__ void __launch_bounds__(NTH, 1) __cluster_dims__(2, 1, 1)
lstm_anom_kernel(const float* __restrict__ x,
                 const float* __restrict__ Wih,
                 const float* __restrict__ Whh,
                 const float* __restrict__ bih,
                 const float* __restrict__ bhh,
                 const float* __restrict__ Wout,
                 const float* __restrict__ bout,
                 float* __restrict__ out)
{
    extern __shared__ char smem[];
    ulonglong2* Wsm2 = (ulonglong2*)(smem + OFF_WSM);
    float4* gb4  = (float4*)(smem + OFF_GB);
    const float* gbf = (const float*)(smem + OFF_GB);
    float*  pwf  = (float*)(smem + OFF_PW);
    float*  prfp = (float*)(smem + OFF_PRFP);
    float*  xqf  = (float*)(smem + OFF_XQ);
    float*  wihs = (float*)(smem + OFF_WIH);
    float4* w04  = (float4*)(smem + OFF_W04);
    float*  wo   = (float*)(smem + OFF_WO);
    float2* b2   = (float2*)(smem + OFF_B2);

    const int tid       = threadIdx.x;
    const uint32_t rank = (uint32_t)(blockIdx.x & 1);
    const uint32_t peer = rank ^ 1u;
    const int cluster   = blockIdx.x >> 1;
    const int row0      = cluster * 4;

    const uint32_t smem_b = (uint32_t)__cvta_generic_to_shared(smem);
    const uint32_t mbar_b = smem_b + OFF_MBAR;
    uint32_t peer_b;
    asm("mapa.shared::cluster.u32 %0, %1, %2;" : "=r"(peer_b) : "r"(smem_b), "r"(peer));
    const uint32_t peer_mbar = peer_b + OFF_MBAR;

    // ---------- roles ----------
    const bool active = (tid < 328);
    const int u = (tid >= 164) ? 1 : 0;        // k sub-window
    const int g = active ? (tid - u * 164) : 0;
    const int prank = (int)(rank ^ 1u);

    // ---------- one-time init ----------
    ull wLA[RPL], wLB[RPL], wPA[RPP], wPB[RPP];
    if (active) {
        int gt  = g / JH;
        int jj0 = g - gt * JH;
        int RA  = gt * Hh + (int)rank * JH + jj0;        // gate i (gt0) / f (gt1)
        int RB  = (gt + 2) * Hh + (int)rank * JH + jj0;  // gate g / o
        const ull* wrA = (const ull*)(Whh + (size_t)RA * Hh);
        const ull* wrB = (const ull*)(Whh + (size_t)RB * Hh);
        {   // phase L weights: local k-half
            int kb = (int)rank * 41 + u * 21;
#pragma unroll
            for (int kk = 0; kk < 21; kk++) {
                bool real = (u * 21 + kk) < 41;
                ull vAw = real ? wrA[kb + kk] : 0ull;
                ull vBw = real ? wrB[kb + kk] : 0ull;
                if (kk < RPL) { wLA[kk] = vAw; wLB[kk] = vBw; }
                else Wsm2[(kk - RPL) * 328 + tid] = make_ulonglong2(vAw, vBw);
            }
        }
        {   // phase P weights: peer k-half
            int kb = prank * 41 + u * 21;
#pragma unroll
            for (int kk = 0; kk < 21; kk++) {
                bool real = (u * 21 + kk) < 41;
                ull vAw = real ? wrA[kb + kk] : 0ull;
                ull vBw = real ? wrB[kb + kk] : 0ull;
                if (kk < RPP) { wPA[kk] = vAw; wPB[kk] = vBw; }
                else Wsm2[(SPL + kk - RPP) * 328 + tid] = make_ulonglong2(vAw, vBw);
            }
        }
        if (u == 0) {
#pragma unroll
            for (int i = 1; i < 8; i++) {
                wihs[(0 * 7 + i - 1) * 164 + g] = Wih[RA * 8 + i];
                wihs[(1 * 7 + i - 1) * 164 + g] = Wih[RB * 8 + i];
            }
            b2[g] = make_float2(bih[RA] + bhh[RA], bih[RB] + bhh[RB]);
        }
    }
    if (tid < JH) {
        int base = (int)rank * JH + tid;
        w04[tid] = make_float4(Wih[(0 * Hh + base) * 8], Wih[(1 * Hh + base) * 8],
                               Wih[(2 * Hh + base) * 8], Wih[(3 * Hh + base) * 8]);
        wo[tid] = Wout[base];
    }
    for (int idx = tid; idx < (SZ_HQ / 4); idx += NTH)
        ((float*)(smem + OFF_HQ))[idx] = 0.f;
    for (int idx = tid; idx < (SZ_PW / 4); idx += NTH) pwf[idx] = 0.f;
    if (tid < 8) prfp[tid] = 0.f;
    if (tid < 32) {
        int i = tid >> 2, r = tid & 3;
        xqf[(0 * 8 + i) * 4 + r] = x[((size_t)((row0 + r) * Tt)) * 8 + i];
    }
    if (tid == 0) {
        // per phase: 1 self-arm + 4 peer pred arrives (h comes as 1312B tx)
        asm volatile("mbarrier.init.shared.b64 [%0], 5;" :: "r"(mbar_b) : "memory");
        asm volatile("mbarrier.init.shared.b64 [%0], 5;" :: "r"(mbar_b + 8) : "memory");
    }
    const float bout_r = bout[0];
    float c_r = 0.f;
    const int jj = tid >> 2, rr = tid & 3;
    const int wid = tid >> 5, lane = tid & 31;
    int ph0 = 0, ph1 = 0;

    __syncthreads();
    asm volatile("barrier.cluster.arrive.aligned;" ::: "memory");
    asm volatile("barrier.cluster.wait.aligned;" ::: "memory");

    for (int t = 0; t < Tt; ++t) {
        const int cur = t & 1;
        const int nxt = cur ^ 1;

        // ---- crew (warp 11 idle lanes):
        //      lane 356: arm my mbar for next phase + bulk-push h[cur] local half;
        //      lanes 357-360: pred sums (11-term pwf) push. ----
        if (tid >= 356) {
            if (tid == 356) {
                if (t + 1 < Tt) mbar_arrive_expect_tx(mbar_b + (uint32_t)(nxt * 8), HPUSH);
                else            mbar_arrive_local(mbar_b + (uint32_t)(nxt * 8));
                if (t) {
                    uint32_t off = (uint32_t)(OFF_HQ + cur * HBUF + (int)rank * HPUSH);
                    asm volatile("fence.proxy.async.shared::cta;" ::: "memory");
                    bulk_push_peer(peer_b + off, smem_b + off, HPUSH,
                                   peer_mbar + (uint32_t)(cur * 8));
                }
            } else if (tid < 361 && t) {
                int r = tid - 357;
                float s = 0.f;
#pragma unroll
                for (int w = 0; w < 11; w++) s += pwf[nxt * 44 + w * 4 + r];
                st_remote_f32d(peer_b + (uint32_t)(OFF_PRFP + (nxt * 4 + r) * 4), s);
                mbar_arrive_release(peer_mbar + (uint32_t)(cur * 8));
            }
        }

        // ---- phase L: GEMV over LOCAL k sub-window (21 k-pairs, 8 in regs) ----
        ull acc[8];   // [0..3] = row A r0..3, [4..7] = row B
        if (active) {
            const float4* xv4 = (const float4*)(smem + OFF_XQ + cur * 128);
            if (u == 0) {
                float2 bb = b2[g];
                float a0 = bb.x, a1 = bb.x, a2 = bb.x, a3 = bb.x;
                float b0 = bb.y, b1 = bb.y, b2v = bb.y, b3 = bb.y;
#pragma unroll
                for (int i = 1; i < 5; i++) {     // features 1-4
                    float4 xv = xv4[i];
                    float wA = wihs[(0 * 7 + i - 1) * 164 + g];
                    float wB = wihs[(1 * 7 + i - 1) * 164 + g];
                    a0 += wA * xv.x; a1 += wA * xv.y; a2 += wA * xv.z; a3 += wA * xv.w;
                    b0 += wB * xv.x; b1 += wB * xv.y; b2v += wB * xv.z; b3 += wB * xv.w;
                }
                acc[0] = pack2_(a0, 0.f); acc[1] = pack2_(a1, 0.f);
                acc[2] = pack2_(a2, 0.f); acc[3] = pack2_(a3, 0.f);
                acc[4] = pack2_(b0, 0.f); acc[5] = pack2_(b1, 0.f);
                acc[6] = pack2_(b2v, 0.f); acc[7] = pack2_(b3, 0.f);
            } else {
                float a0 = 0.f, a1 = 0.f, a2 = 0.f, a3 = 0.f;
                float b0 = 0.f, b1 = 0.f, b2v = 0.f, b3 = 0.f;
#pragma unroll
                for (int i = 5; i < 8; i++) {     // features 5-7
                    float4 xv = xv4[i];
                    float wA = wihs[(0 * 7 + i - 1) * 164 + g];
                    float wB = wihs[(1 * 7 + i - 1) * 164 + g];
                    a0 += wA * xv.x; a1 += wA * xv.y; a2 += wA * xv.z; a3 += wA * xv.w;
                    b0 += wB * xv.x; b1 += wB * xv.y; b2v += wB * xv.z; b3 += wB * xv.w;
                }
                acc[0] = pack2_(a0, 0.f); acc[1] = pack2_(a1, 0.f);
                acc[2] = pack2_(a2, 0.f); acc[3] = pack2_(a3, 0.f);
                acc[4] = pack2_(b0, 0.f); acc[5] = pack2_(b1, 0.f);
                acc[6] = pack2_(b2v, 0.f); acc[7] = pack2_(b3, 0.f);
            }
            const char* hbL = smem + OFF_HQ + cur * HBUF + ((int)rank * 41 + u * 21) * 32;
#pragma unroll
            for (int kk = 0; kk < RPL; kk++) {
                ulonglong2 h01 = *(const ulonglong2*)(hbL + kk * 32);
                ulonglong2 h23 = *(const ulonglong2*)(hbL + kk * 32 + 16);
                fma2_(acc[0], wLA[kk], h01.x); fma2_(acc[4], wLB[kk], h01.x);
                fma2_(acc[1], wLA[kk], h01.y); fma2_(acc[5], wLB[kk], h01.y);
                fma2_(acc[2], wLA[kk], h23.x); fma2_(acc[6], wLB[kk], h23.x);
                fma2_(acc[3], wLA[kk], h23.y); fma2_(acc[7], wLB[kk], h23.y);
            }
#pragma unroll
            for (int kk = RPL; kk < 21; kk++) {
                ulonglong2 w2 = Wsm2[(kk - RPL) * 328 + tid];
                ulonglong2 h01 = *(const ulonglong2*)(hbL + kk * 32);
                ulonglong2 h23 = *(const ulonglong2*)(hbL + kk * 32 + 16);
                fma2_(acc[0], w2.x, h01.x); fma2_(acc[4], w2.y, h01.x);
                fma2_(acc[1], w2.x, h01.y); fma2_(acc[5], w2.y, h01.y);
                fma2_(acc[2], w2.x, h23.x); fma2_(acc[6], w2.y, h23.x);
                fma2_(acc[3], w2.x, h23.y); fma2_(acc[7], w2.y, h23.y);
            }
        }

        // ---- wait for peer h-half (bulk tx) + pred (pushed this step by peer) ----
        if (t && (active || (tid >= 352 && tid < 356))) {
            uint32_t p = cur ? (uint32_t)ph1 : (uint32_t)ph0;
            mbar_wait(mbar_b + (uint32_t)(cur * 8), p);
            if (cur) ph1 ^= 1; else ph0 ^= 1;
        }

        if (active) {
            // ---- phase P: GEMV over PEER k sub-window (21 k-pairs, 14 in regs) ----
            const char* hbP = smem + OFF_HQ + cur * HBUF + (prank * 41 + u * 21) * 32;
#pragma unroll
            for (int kk = 0; kk < RPP; kk++) {
                ulonglong2 h01 = *(const ulonglong2*)(hbP + kk * 32);
                ulonglong2 h23 = *(const ulonglong2*)(hbP + kk * 32 + 16);
                fma2_(acc[0], wPA[kk], h01.x); fma2_(acc[4], wPB[kk], h01.x);
                fma2_(acc[1], wPA[kk], h01.y); fma2_(acc[5], wPB[kk], h01.y);
                fma2_(acc[2], wPA[kk], h23.x); fma2_(acc[6], wPB[kk], h23.x);
                fma2_(acc[3], wPA[kk], h23.y); fma2_(acc[7], wPB[kk], h23.y);
            }
#pragma unroll
            for (int kk = RPP; kk < 21; kk++) {
                ulonglong2 w2 = Wsm2[(SPL + kk - RPP) * 328 + tid];
                ulonglong2 h01 = *(const ulonglong2*)(hbP + kk * 32);
                ulonglong2 h23 = *(const ulonglong2*)(hbP + kk * 32 + 16);
                fma2_(acc[0], w2.x, h01.x); fma2_(acc[4], w2.y, h01.x);
                fma2_(acc[1], w2.x, h01.y); fma2_(acc[5], w2.y, h01.y);
                fma2_(acc[2], w2.x, h23.x); fma2_(acc[6], w2.y, h23.x);
                fma2_(acc[3], w2.x, h23.y); fma2_(acc[7], w2.y, h23.y);
            }
            float lo, hi;
            float4 vA, vB;
            unpack2_(acc[0], lo, hi); vA.x = lo + hi;
            unpack2_(acc[1], lo, hi); vA.y = lo + hi;
            unpack2_(acc[2], lo, hi); vA.z = lo + hi;
            unpack2_(acc[3], lo, hi); vA.w = lo + hi;
            unpack2_(acc[4], lo, hi); vB.x = lo + hi;
            unpack2_(acc[5], lo, hi); vB.y = lo + hi;
            unpack2_(acc[6], lo, hi); vB.z = lo + hi;
            unpack2_(acc[7], lo, hi); vB.w = lo + hi;
            gb4[(u * 2 + 0) * 164 + g] = vA;
            gb4[(u * 2 + 1) * 164 + g] = vB;
        } else if (tid >= 352 && tid < 356) {
            // ---- pred finalize + anomaly x0 fix + gmem outputs ----
            int r = tid - 352, row = row0 + r;
            if (t > 0) {
                float sown = 0.f;
#pragma unroll
                for (int w = 0; w < 11; w++) sown += pwf[nxt * 44 + w * 4 + r];
                float pred = sown + prfp[nxt * 4 + r] + bout_r;
                float x0raw = xqf[(cur * 8 + 0) * 4 + r];
                float flag = 0.f, x0 = x0raw;
                if (fabsf(pred - x0raw) > 0.1f) { x0 = pred; flag = 1.f; }
                xqf[(cur * 8 + 0) * 4 + r] = x0;
                if (rank == 0) {
                    out[(size_t)row * Tt + (t - 1)] = pred;
                    out[(size_t)Bb * Tt + (size_t)row * Tt + t] = flag;
                }
            } else if (rank == 0) {
                out[(size_t)Bb * Tt + (size_t)row * Tt] = 0.f;
            }
        } else if (tid >= 361 && tid < 365 && (t + 1 < Tt)) {
            // ---- x prefetch (4 lanes x 2 features) ----
            int i = tid - 361;
#pragma unroll
            for (int r = 0; r < 4; r++) {
                xqf[(nxt * 8 + i) * 4 + r] =
                    x[((size_t)((row0 + r) * Tt + t + 1)) * 8 + i];
                xqf[(nxt * 8 + i + 4) * 4 + r] =
                    x[((size_t)((row0 + r) * Tt + t + 1)) * 8 + i + 4];
            }
        }
        __syncthreads();   // gate partials + fixed x0 + xqf[nxt] published

        // ---- activation, state update, LOCAL h store, pred partials ----
        if (active) {
            float x0 = xqf[(cur * 8 + 0) * 4 + rr];
            float4 wz = w04[jj];
            float gi = gbf[((0 * 2 + 0) * 164 + jj) * 4 + rr]
                     + gbf[((1 * 2 + 0) * 164 + jj) * 4 + rr] + wz.x * x0;
            float gF = gbf[((0 * 2 + 0) * 164 + jj + 82) * 4 + rr]
                     + gbf[((1 * 2 + 0) * 164 + jj + 82) * 4 + rr] + wz.y * x0;
            float gg = gbf[((0 * 2 + 1) * 164 + jj) * 4 + rr]
                     + gbf[((1 * 2 + 1) * 164 + jj) * 4 + rr] + wz.z * x0;
            float go = gbf[((0 * 2 + 1) * 164 + jj + 82) * 4 + rr]
                     + gbf[((1 * 2 + 1) * 164 + jj + 82) * 4 + rr] + wz.w * x0;
            float iv = sigmoidf_(gi);
            float fv = sigmoidf_(gF);
            float gv = tanhf(gg);
            float ov = sigmoidf_(go);
            c_r = fv * c_r + iv * gv;
            float hn = ov * tanhf(c_r);

            int kg = (int)rank * JH + jj;
            *(float*)(smem + OFF_HQ + nxt * HBUF
                      + (kg >> 1) * 32 + rr * 8 + (kg & 1) * 4) = hn;   // local only

            float p = hn * wo[jj];
            if (wid < 10) {
                p += __shfl_xor_sync(0xffffffffu, p, 16);
                p += __shfl_xor_sync(0xffffffffu, p, 8);
                p += __shfl_xor_sync(0xffffffffu, p, 4);
            } else {
                p += __shfl_xor_sync(0xffu, p, 4);
            }
            if (lane < 4) pwf[cur * 44 + wid * 4 + lane] = p;
        }
        __syncthreads();   // h[nxt] + pwf[cur] published
    }

    // ---- tail: push final pred sums (phase Tt on mbar[0]), write col Tt-1 ----
    if (tid >= 357 && tid < 361) {
        int r = tid - 357;
        float s = 0.f;
#pragma unroll
        for (int w = 0; w < 11; w++) s += pwf[1 * 44 + w * 4 + r];
        st_remote_f32d(peer_b + (uint32_t)(OFF_PRFP + (1 * 4 + r) * 4), s);
        mbar_arrive_release(peer_mbar);
    }
    if (tid >= 352 && tid < 356) {
        mbar_wait(mbar_b, (uint32_t)ph0);
        if (rank == 0) {
            int r = tid - 352;
            float so = 0.f;
#pragma unroll
            for (int w = 0; w < 11; w++) so += pwf[1 * 44 + w * 4 + r];
            float pred = so + prfp[1 * 4 + r] + bout_r;
            out[(size_t)(row0 + r) * Tt + (Tt - 1)] = pred;
        }
    }
}

extern "C" void kernel_launch(void* const* d_in, const int* in_sizes, int n_in,
                              void* d_out, int out_size) {
    (void)in_sizes; (void)n_in; (void)out_size;
    cudaFuncSetAttribute(lstm_anom_kernel,
                         cudaFuncAttributeMaxDynamicSharedMemorySize, SMEM_TOTAL);
    lstm_anom_kernel<<<NCTA, NTH, SMEM_TOTAL>>>(
        (const float*)d_in[0],   // x
        (const float*)d_in[1],   // W_ih
        (const float*)d_in[2],   // W_hh
        (const float*)d_in[3],   // b_ih
        (const float*)d_in[4],   // b_hh
        (const float*)d_in[5],   // W_out
        (const float*)d_in[6],   // b_out
        (float*)d_out);
}

// round 17
// speedup vs baseline: 1.1757x; 1.0471x over previous
#include <cuda_runtime.h>
#include <cstdint>
#include <math.h>

// Problem constants
#define Bb   256
#define Tt   1024
#define Hh   164
#define JH   82          // hidden slice per CTA (M-split across 2-CTA cluster)
#define NTH  384         // 12 warps; 328 compute threads
#define NCTA 128         // 64 clusters x 2
#define HSL  84          // h k-pair slots per parity (82 real + 2 zero pad)
#define HBUF (HSL * 32)  // 2688
#define RPW  11          // k-pairs in registers per window
#define SPW  10          // k-pairs in smem per window
#define HPUSH 1312       // bytes per h half-push (41 k-pairs * 32B)

// shared memory layout (bytes)
#define OFF_WSM   0
#define SZ_WSM    (2 * SPW * 328 * 16)      // 104960
#define OFF_HQ    (OFF_WSM + SZ_WSM)        // 104960 (16B aligned)
#define SZ_HQ     (2 * HBUF)                // 5376
#define OFF_GB    (OFF_HQ + SZ_HQ)          // 110336
#define SZ_GB     (656 * 16)                // 10496: gb4[(u*2+ab)*164+g]
#define OFF_PW    (OFF_GB + SZ_GB)          // 120832
#define SZ_PW     (2 * 11 * 32)             // 704: pwf[par][w][8] (2 entries/row)
#define OFF_PRFP  (OFF_PW + SZ_PW)          // peer pred sums [par][r]
#define SZ_PRFP   32
#define OFF_XQ    (OFF_PRFP + SZ_PRFP)
#define SZ_XQ     (2 * 8 * 16)              // 256
#define OFF_WIH   (OFF_XQ + SZ_XQ)          // wihs[(ab*7+i-1)*164+g]
#define SZ_WIH    (14 * 164 * 4)            // 9184
#define OFF_W04   (OFF_WIH + SZ_WIH)        // w_ih[:,0] float4 per jj
#define SZ_W04    (82 * 16)
#define OFF_WO    (OFF_W04 + SZ_W04)
#define SZ_WO     (82 * 4)
#define OFF_B2    (OFF_WO + SZ_WO)          // (biasA,biasB) per g
#define SZ_B2     (164 * 8)
#define OFF_MBAR  ((OFF_B2 + SZ_B2 + 15) & ~15)
#define SMEM_TOTAL (OFF_MBAR + 16)

typedef unsigned long long ull;

__device__ __forceinline__ float sigmoidf_(float v) {
    return 1.0f / (1.0f + expf(-v));
}
__device__ __forceinline__ ull pack2_(float a, float b) {
    ull r; asm("mov.b64 %0, {%1, %2};" : "=l"(r) : "f"(a), "f"(b)); return r;
}
__device__ __forceinline__ void unpack2_(ull v, float& a, float& b) {
    asm("mov.b64 {%0, %1}, %2;" : "=f"(a), "=f"(b) : "l"(v));
}
__device__ __forceinline__ void fma2_(ull& acc, ull a, ull b) {
    asm("fma.rn.f32x2 %0, %1, %2, %0;" : "+l"(acc) : "l"(a), "l"(b));
}
__device__ __forceinline__ void st_remote_f32d(uint32_t raddr, float v) {
    asm volatile("st.shared::cluster.f32 [%0], %1;" :: "r"(raddr), "f"(v) : "memory");
}
__device__ __forceinline__ void mbar_arrive_release(uint32_t remote_mbar) {
    asm volatile("mbarrier.arrive.release.cluster.shared::cluster.b64 _, [%0];"
                 :: "r"(remote_mbar) : "memory");
}
__device__ __forceinline__ void mbar_arrive_expect_tx(uint32_t mbar, uint32_t tx) {
    asm volatile("mbarrier.arrive.expect_tx.shared.b64 _, [%0], %1;"
                 :: "r"(mbar), "r"(tx) : "memory");
}
__device__ __forceinline__ void mbar_arrive_local(uint32_t mbar) {
    asm volatile("mbarrier.arrive.shared.b64 _, [%0];" :: "r"(mbar) : "memory");
}
__device__ __forceinline__ void bulk_push_peer(uint32_t peer_dst, uint32_t local_src,
                                               uint32_t bytes, uint32_t peer_mbar) {
    asm volatile(
        "cp.async.bulk.shared::cluster.shared::cta.mbarrier::complete_tx::bytes "
        "[%0], [%1], %2, [%3];"
        :: "r"(peer_dst), "r"(local_src), "r"(bytes), "r"(peer_mbar) : "memory");
}
__device__ __forceinline__ void mbar_wait(uint32_t mbar, uint32_t parity) {
    uint32_t done;
    asm volatile(
        "{\n\t.reg .pred p;\n\t"
        "mbarrier.try_wait.parity.acquire.cluster.shared::cta.b64 p, [%1], %2;\n\t"
        "selp.b32 %0, 1, 0, p;\n\t}"
        : "=r"(done) : "r"(mbar), "r"(parity) : "memory");
    while (!done) {
        asm volatile(
            "{\n\t.reg .pred p;\n\t"
            "mbarrier.try_wait.parity.acquire.cluster.shared::cta.b64 p, [%1], %2, 0x989680;\n\t"
            "selp.b32 %0, 1, 0, p;\n\t}"
            : "=r"(done) : "r"(mbar), "r"(parity) : "memory");
    }
}

extern "C" __global__ void __launch_bounds__(NTH, 1) __cluster_dims__(2, 1, 1)
lstm_anom_kernel(const float* __restrict__ x,
                 const float* __restrict__ Wih,
                 const float* __restrict__ Whh,
                 const float* __restrict__ bih,
                 const float* __restrict__ bhh,
                 const float* __restrict__ Wout,
                 const float* __restrict__ bout,
                 float* __restrict__ out)
{
    extern __shared__ char smem[];
    ulonglong2* Wsm2 = (ulonglong2*)(smem + OFF_WSM);
    float4* gb4  = (float4*)(smem + OFF_GB);
    const float* gbf = (const float*)(smem + OFF_GB);
    float*  pwf  = (float*)(smem + OFF_PW);
    float*  prfp = (float*)(smem + OFF_PRFP);
    float*  xqf  = (float*)(smem + OFF_XQ);
    float*  wihs = (float*)(smem + OFF_WIH);
    float4* w04  = (float4*)(smem + OFF_W04);
    float*  wo   = (float*)(smem + OFF_WO);
    float2* b2   = (float2*)(smem + OFF_B2);

    const int tid       = threadIdx.x;
    const uint32_t rank = (uint32_t)(blockIdx.x & 1);
    const uint32_t peer = rank ^ 1u;
    const int cluster   = blockIdx.x >> 1;
    const int row0      = cluster * 4;

    const uint32_t smem_b = (uint32_t)__cvta_generic_to_shared(smem);
    const uint32_t mbar_b = smem_b + OFF_MBAR;
    uint32_t peer_b;
    asm("mapa.shared::cluster.u32 %0, %1, %2;" : "=r"(peer_b) : "r"(smem_b), "r"(peer));
    const uint32_t peer_mbar = peer_b + OFF_MBAR;

    // ---------- roles ----------
    const bool active = (tid < 328);
    const int u = (tid >= 164) ? 1 : 0;        // k sub-window
    const int g = active ? (tid - u * 164) : 0;
    const int prank = (int)(rank ^ 1u);

    // ---------- one-time init ----------
    ull wLA[RPW], wLB[RPW], wPA[RPW], wPB[RPW];
    if (active) {
        int gt  = g / JH;
        int jj0 = g - gt * JH;
        int RA  = gt * Hh + (int)rank * JH + jj0;        // gate i (gt0) / f (gt1)
        int RB  = (gt + 2) * Hh + (int)rank * JH + jj0;  // gate g / o
        const ull* wrA = (const ull*)(Whh + (size_t)RA * Hh);
        const ull* wrB = (const ull*)(Whh + (size_t)RB * Hh);
#pragma unroll
        for (int w = 0; w < 2; w++) {
            int half = w ? prank : (int)rank;
            int kb = half * 41 + u * 21;
#pragma unroll
            for (int kk = 0; kk < 21; kk++) {
                bool real = (u * 21 + kk) < 41;
                ull vAw = real ? wrA[kb + kk] : 0ull;
                ull vBw = real ? wrB[kb + kk] : 0ull;
                if (kk < RPW) {
                    if (w == 0) { wLA[kk] = vAw; wLB[kk] = vBw; }
                    else        { wPA[kk] = vAw; wPB[kk] = vBw; }
                } else {
                    Wsm2[(w * SPW + kk - RPW) * 328 + tid] = make_ulonglong2(vAw, vBw);
                }
            }
        }
        if (u == 0) {
#pragma unroll
            for (int i = 1; i < 8; i++) {
                wihs[(0 * 7 + i - 1) * 164 + g] = Wih[RA * 8 + i];
                wihs[(1 * 7 + i - 1) * 164 + g] = Wih[RB * 8 + i];
            }
            b2[g] = make_float2(bih[RA] + bhh[RA], bih[RB] + bhh[RB]);
        }
    }
    if (tid < JH) {
        int base = (int)rank * JH + tid;
        w04[tid] = make_float4(Wih[(0 * Hh + base) * 8], Wih[(1 * Hh + base) * 8],
                               Wih[(2 * Hh + base) * 8], Wih[(3 * Hh + base) * 8]);
        wo[tid] = Wout[base];
    }
    for (int idx = tid; idx < (SZ_HQ / 4); idx += NTH)
        ((float*)(smem + OFF_HQ))[idx] = 0.f;
    for (int idx = tid; idx < (SZ_PW / 4); idx += NTH) pwf[idx] = 0.f;
    if (tid < 8) prfp[tid] = 0.f;
    if (tid < 32) {
        int i = tid >> 2, r = tid & 3;
        xqf[(0 * 8 + i) * 4 + r] = x[((size_t)((row0 + r) * Tt)) * 8 + i];
    }
    if (tid == 0) {
        // per phase: 1 self-arm + 4 peer pred arrives (h comes as 1312B tx)
        asm volatile("mbarrier.init.shared.b64 [%0], 5;" :: "r"(mbar_b) : "memory");
        asm volatile("mbarrier.init.shared.b64 [%0], 5;" :: "r"(mbar_b + 8) : "memory");
    }
    const float bout_r = bout[0];
    float c_r = 0.f;
    const int jj = tid >> 2, rr = tid & 3;
    const int wid = tid >> 5, lane = tid & 31;
    int ph0 = 0, ph1 = 0;

    __syncthreads();
    asm volatile("barrier.cluster.arrive.aligned;" ::: "memory");
    asm volatile("barrier.cluster.wait.aligned;" ::: "memory");

    for (int t = 0; t < Tt; ++t) {
        const int cur = t & 1;
        const int nxt = cur ^ 1;

        // ---- crew (warp 11 idle lanes):
        //      lane 356: arm my mbar for next phase + bulk-push h[cur] local half;
        //      lanes 357-360: pred sums (22-entry pwf) push. ----
        if (tid >= 356) {
            if (tid == 356) {
                if (t + 1 < Tt) mbar_arrive_expect_tx(mbar_b + (uint32_t)(nxt * 8), HPUSH);
                else            mbar_arrive_local(mbar_b + (uint32_t)(nxt * 8));
                if (t) {
                    uint32_t off = (uint32_t)(OFF_HQ + cur * HBUF + (int)rank * HPUSH);
                    asm volatile("fence.proxy.async.shared::cta;" ::: "memory");
                    bulk_push_peer(peer_b + off, smem_b + off, HPUSH,
                                   peer_mbar + (uint32_t)(cur * 8));
                }
            } else if (tid < 361 && t) {
                int r = tid - 357;
                float s = 0.f;
#pragma unroll
                for (int w = 0; w < 11; w++) {
                    s += pwf[nxt * 88 + w * 8 + r];
                    s += pwf[nxt * 88 + w * 8 + 4 + r];
                }
                st_remote_f32d(peer_b + (uint32_t)(OFF_PRFP + (nxt * 4 + r) * 4), s);
                mbar_arrive_release(peer_mbar + (uint32_t)(cur * 8));
            }
        }

        // ---- phase L: GEMV over LOCAL k sub-window (21 k-pairs) ----
        ull acc[8];   // [0..3] = row A r0..3, [4..7] = row B
        if (active) {
            if (u == 0) {
                float2 bb = b2[g];
                float a0 = bb.x, a1 = bb.x, a2 = bb.x, a3 = bb.x;
                float b0 = bb.y, b1 = bb.y, b2v = bb.y, b3 = bb.y;
                const float4* xv4 = (const float4*)(smem + OFF_XQ + cur * 128);
#pragma unroll
                for (int i = 1; i < 8; i++) {
                    float4 xv = xv4[i];
                    float wA = wihs[(0 * 7 + i - 1) * 164 + g];
                    float wB = wihs[(1 * 7 + i - 1) * 164 + g];
                    a0 += wA * xv.x; a1 += wA * xv.y; a2 += wA * xv.z; a3 += wA * xv.w;
                    b0 += wB * xv.x; b1 += wB * xv.y; b2v += wB * xv.z; b3 += wB * xv.w;
                }
                acc[0] = pack2_(a0, 0.f); acc[1] = pack2_(a1, 0.f);
                acc[2] = pack2_(a2, 0.f); acc[3] = pack2_(a3, 0.f);
                acc[4] = pack2_(b0, 0.f); acc[5] = pack2_(b1, 0.f);
                acc[6] = pack2_(b2v, 0.f); acc[7] = pack2_(b3, 0.f);
            } else {
#pragma unroll
                for (int q = 0; q < 8; q++) acc[q] = 0ull;
            }
            const char* hbL = smem + OFF_HQ + cur * HBUF + ((int)rank * 41 + u * 21) * 32;
#pragma unroll
            for (int kk = 0; kk < RPW; kk++) {
                ulonglong2 h01 = *(const ulonglong2*)(hbL + kk * 32);
                ulonglong2 h23 = *(const ulonglong2*)(hbL + kk * 32 + 16);
                fma2_(acc[0], wLA[kk], h01.x); fma2_(acc[4], wLB[kk], h01.x);
                fma2_(acc[1], wLA[kk], h01.y); fma2_(acc[5], wLB[kk], h01.y);
                fma2_(acc[2], wLA[kk], h23.x); fma2_(acc[6], wLB[kk], h23.x);
                fma2_(acc[3], wLA[kk], h23.y); fma2_(acc[7], wLB[kk], h23.y);
            }
#pragma unroll
            for (int kk = RPW; kk < 21; kk++) {
                ulonglong2 w2 = Wsm2[(0 * SPW + kk - RPW) * 328 + tid];
                ulonglong2 h01 = *(const ulonglong2*)(hbL + kk * 32);
                ulonglong2 h23 = *(const ulonglong2*)(hbL + kk * 32 + 16);
                fma2_(acc[0], w2.x, h01.x); fma2_(acc[4], w2.y, h01.x);
                fma2_(acc[1], w2.x, h01.y); fma2_(acc[5], w2.y, h01.y);
                fma2_(acc[2], w2.x, h23.x); fma2_(acc[6], w2.y, h23.x);
                fma2_(acc[3], w2.x, h23.y); fma2_(acc[7], w2.y, h23.y);
            }
        }

        // ---- wait for peer h-half (bulk tx) + pred (pushed this step by peer) ----
        if (t && (active || (tid >= 352 && tid < 356))) {
            uint32_t p = cur ? (uint32_t)ph1 : (uint32_t)ph0;
            mbar_wait(mbar_b + (uint32_t)(cur * 8), p);
            if (cur) ph1 ^= 1; else ph0 ^= 1;
        }

        if (active) {
            // ---- phase P: GEMV over PEER k sub-window ----
            const char* hbP = smem + OFF_HQ + cur * HBUF + (prank * 41 + u * 21) * 32;
#pragma unroll
            for (int kk = 0; kk < RPW; kk++) {
                ulonglong2 h01 = *(const ulonglong2*)(hbP + kk * 32);
                ulonglong2 h23 = *(const ulonglong2*)(hbP + kk * 32 + 16);
                fma2_(acc[0], wPA[kk], h01.x); fma2_(acc[4], wPB[kk], h01.x);
                fma2_(acc[1], wPA[kk], h01.y); fma2_(acc[5], wPB[kk], h01.y);
                fma2_(acc[2], wPA[kk], h23.x); fma2_(acc[6], wPB[kk], h23.x);
                fma2_(acc[3], wPA[kk], h23.y); fma2_(acc[7], wPB[kk], h23.y);
            }
#pragma unroll
            for (int kk = RPW; kk < 21; kk++) {
                ulonglong2 w2 = Wsm2[(1 * SPW + kk - RPW) * 328 + tid];
                ulonglong2 h01 = *(const ulonglong2*)(hbP + kk * 32);
                ulonglong2 h23 = *(const ulonglong2*)(hbP + kk * 32 + 16);
                fma2_(acc[0], w2.x, h01.x); fma2_(acc[4], w2.y, h01.x);
                fma2_(acc[1], w2.x, h01.y); fma2_(acc[5], w2.y, h01.y);
                fma2_(acc[2], w2.x, h23.x); fma2_(acc[6], w2.y, h23.x);
                fma2_(acc[3], w2.x, h23.y); fma2_(acc[7], w2.y, h23.y);
            }
            float lo, hi;
            float4 vA, vB;
            unpack2_(acc[0], lo, hi); vA.x = lo + hi;
            unpack2_(acc[1], lo, hi); vA.y = lo + hi;
            unpack2_(acc[2], lo, hi); vA.z = lo + hi;
            unpack2_(acc[3], lo, hi); vA.w = lo + hi;
            unpack2_(acc[4], lo, hi); vB.x = lo + hi;
            unpack2_(acc[5], lo, hi); vB.y = lo + hi;
            unpack2_(acc[6], lo, hi); vB.z = lo + hi;
            unpack2_(acc[7], lo, hi); vB.w = lo + hi;
            gb4[(u * 2 + 0) * 164 + g] = vA;
            gb4[(u * 2 + 1) * 164 + g] = vB;
        } else if (tid >= 352 && tid < 356) {
            // ---- pred finalize + anomaly x0 fix + gmem outputs ----
            int r = tid - 352, row = row0 + r;
            if (t > 0) {
                float sown = 0.f;
#pragma unroll
                for (int w = 0; w < 11; w++) {
                    sown += pwf[nxt * 88 + w * 8 + r];
                    sown += pwf[nxt * 88 + w * 8 + 4 + r];
                }
                float pred = sown + prfp[nxt * 4 + r] + bout_r;
                float x0raw = xqf[(cur * 8 + 0) * 4 + r];
                float flag = 0.f, x0 = x0raw;
                if (fabsf(pred - x0raw) > 0.1f) { x0 = pred; flag = 1.f; }
                xqf[(cur * 8 + 0) * 4 + r] = x0;
                if (rank == 0) {
                    out[(size_t)row * Tt + (t - 1)] = pred;
                    out[(size_t)Bb * Tt + (size_t)row * Tt + t] = flag;
                }
            } else if (rank == 0) {
                out[(size_t)Bb * Tt + (size_t)row * Tt] = 0.f;
            }
        } else if (tid >= 361 && tid < 365 && (t + 1 < Tt)) {
            // ---- x prefetch (4 lanes x 2 features) ----
            int i = tid - 361;
#pragma unroll
            for (int r = 0; r < 4; r++) {
                xqf[(nxt * 8 + i) * 4 + r] =
                    x[((size_t)((row0 + r) * Tt + t + 1)) * 8 + i];
                xqf[(nxt * 8 + i + 4) * 4 + r] =
                    x[((size_t)((row0 + r) * Tt + t + 1)) * 8 + i + 4];
            }
        }
        __syncthreads();   // gate partials + fixed x0 + xqf[nxt] published

        // ---- activation, state update, LOCAL h store, pred partials ----
        if (active) {
            float x0 = xqf[(cur * 8 + 0) * 4 + rr];
            float4 wz = w04[jj];
            float gi = gbf[((0 * 2 + 0) * 164 + jj) * 4 + rr]
                     + gbf[((1 * 2 + 0) * 164 + jj) * 4 + rr] + wz.x * x0;
            float gF = gbf[((0 * 2 + 0) * 164 + jj + 82) * 4 + rr]
                     + gbf[((1 * 2 + 0) * 164 + jj + 82) * 4 + rr] + wz.y * x0;
            float gg = gbf[((0 * 2 + 1) * 164 + jj) * 4 + rr]
                     + gbf[((1 * 2 + 1) * 164 + jj) * 4 + rr] + wz.z * x0;
            float go = gbf[((0 * 2 + 1) * 164 + jj + 82) * 4 + rr]
                     + gbf[((1 * 2 + 1) * 164 + jj + 82) * 4 + rr] + wz.w * x0;
            float iv = sigmoidf_(gi);
            float fv = sigmoidf_(gF);
            float gv = tanhf(gg);
            float ov = sigmoidf_(go);
            c_r = fv * c_r + iv * gv;
            float hn = ov * tanhf(c_r);

            int kg = (int)rank * JH + jj;
            *(float*)(smem + OFF_HQ + nxt * HBUF
                      + (kg >> 1) * 32 + rr * 8 + (kg & 1) * 4) = hn;   // local only

            // pred partial: 2 shfls only; 8 lanes store (2 entries per row)
            float p = hn * wo[jj];
            if (wid < 10) {
                p += __shfl_xor_sync(0xffffffffu, p, 16);
                p += __shfl_xor_sync(0xffffffffu, p, 8);
            }
            if (lane < 8) pwf[cur * 88 + wid * 8 + lane] = p;
        }
        __syncthreads();   // h[nxt] + pwf[cur] published
    }

    // ---- tail: push final pred sums (phase Tt on mbar[0]), write col Tt-1 ----
    if (tid >= 357 && tid < 361) {
        int r = tid - 357;
        float s = 0.f;
#pragma unroll
        for (int w = 0; w < 11; w++) {
            s += pwf[1 * 88 + w * 8 + r];
            s += pwf[1 * 88 + w * 8 + 4 + r];
        }
        st_remote_f32d(peer_b + (uint32_t)(OFF_PRFP + (1 * 4 + r) * 4), s);
        mbar_arrive_release(peer_mbar);
    }
    if (tid >= 352 && tid < 356) {
        mbar_wait(mbar_b, (uint32_t)ph0);
        if (rank == 0) {
            int r = tid - 352;
            float so = 0.f;
#pragma unroll
            for (int w = 0; w < 11; w++) {
                so += pwf[1 * 88 + w * 8 + r];
                so += pwf[1 * 88 + w * 8 + 4 + r];
            }
            float pred = so + prfp[1 * 4 + r] + bout_r;
            out[(size_t)(row0 + r) * Tt + (Tt - 1)] = pred;
        }
    }
}

extern "C" void kernel_launch(void* const* d_in, const int* in_sizes, int n_in,
                              void* d_out, int out_size) {
    (void)in_sizes; (void)n_in; (void)out_size;
    cudaFuncSetAttribute(lstm_anom_kernel,
                         cudaFuncAttributeMaxDynamicSharedMemorySize, SMEM_TOTAL);
    lstm_anom_kernel<<<NCTA, NTH, SMEM_TOTAL>>>(
        (const float*)d_in[0],   // x
        (const float*)d_in[1],   // W_ih
        (const float*)d_in[2],   // W_hh
        (const float*)d_in[3],   // b_ih
        (const float*)d_in[4],   // b_hh
        (const float*)d_in[5],   // W_out
        (const float*)d_in[6],   // b_out
        (float*)d_out);
}